// round 4
// baseline (speedup 1.0000x reference)
#include <cuda_runtime.h>
#include <cuda_bf16.h>

// Problem constants
#define BB   4
#define LQ   512
#define LK   512
#define DD   256
#define HH   128
#define TQ   16          // q-rows per CTA in attention kernel

// Scratch (static device memory — allocation-free rule)
__device__ float g_qp[BB * LQ * HH];          // [b*512+q][h]   row-major, 1MB
__device__ float g_cp2T[BB * HH * LK];        // [b][h][k]      transposed, 1MB

// ---------------------------------------------------------------------------
// Kernel A: projections.
//   y==0 : g_qp[row][h]        =  dot(query[row], Wq[h])  + bq[h]
//   y==1 : g_cp2T[b][h][k]     = 2*(dot(context[row], Wc[h]) + bc[h])
// Tiled GEMM: 64 rows x 128 h per CTA, K-loop of 32 over D=256.
// ---------------------------------------------------------------------------
__global__ __launch_bounds__(256) void proj_kernel(
    const float* __restrict__ query, const float* __restrict__ context,
    const float* __restrict__ Wq, const float* __restrict__ bq,
    const float* __restrict__ Wc, const float* __restrict__ bc)
{
    const int which = blockIdx.y;
    const float* __restrict__ src  = which ? context : query;
    const float* __restrict__ W    = which ? Wc : Wq;
    const float* __restrict__ bias = which ? bc : bq;
    const float scale = which ? 2.0f : 1.0f;

    __shared__ float As[32][65];    // [k][row]  (padded vs STS conflicts)
    __shared__ float Bs[32][129];   // [k][h]    (padded)

    const int t  = threadIdx.x;
    const int tx = t & 15;          // h-dim lane
    const int ty = t >> 4;          // row-dim lane
    const int l0 = blockIdx.x * 64;

    float acc[4][8];
    #pragma unroll
    for (int i = 0; i < 4; ++i)
        #pragma unroll
        for (int j = 0; j < 8; ++j) acc[i][j] = 0.f;

    for (int it = 0; it < 8; ++it) {
        const int k0 = it * 32;
        // Load A tile: 64 rows x 32 k  (float4-coalesced)
        {
            const int r  = t >> 3;           // 0..31
            const int c4 = (t & 7) * 4;      // 0,4,...,28
            #pragma unroll
            for (int p = 0; p < 2; ++p) {
                const int row = r + p * 32;
                float4 v = *(const float4*)&src[(l0 + row) * DD + k0 + c4];
                As[c4 + 0][row] = v.x; As[c4 + 1][row] = v.y;
                As[c4 + 2][row] = v.z; As[c4 + 3][row] = v.w;
            }
        }
        // Load B tile: 128 h x 32 k
        {
            const int h = t >> 1;            // 0..127
            #pragma unroll
            for (int j = 0; j < 4; ++j) {
                const int f = (t & 1) * 4 + j;   // float4 index 0..7
                float4 v = __ldg((const float4*)&W[h * DD + k0 + f * 4]);
                Bs[f * 4 + 0][h] = v.x; Bs[f * 4 + 1][h] = v.y;
                Bs[f * 4 + 2][h] = v.z; Bs[f * 4 + 3][h] = v.w;
            }
        }
        __syncthreads();
        #pragma unroll
        for (int kk = 0; kk < 32; ++kk) {
            float a[4], bb[8];
            #pragma unroll
            for (int i = 0; i < 4; ++i) a[i] = As[kk][ty + 16 * i];
            #pragma unroll
            for (int j = 0; j < 8; ++j) bb[j] = Bs[kk][tx + 16 * j];
            #pragma unroll
            for (int i = 0; i < 4; ++i)
                #pragma unroll
                for (int j = 0; j < 8; ++j) acc[i][j] = fmaf(a[i], bb[j], acc[i][j]);
        }
        __syncthreads();
    }

    // Epilogue
    #pragma unroll
    for (int j = 0; j < 8; ++j) {
        const int h = tx + 16 * j;
        const float bv_ = bias[h];
        #pragma unroll
        for (int i = 0; i < 4; ++i) {
            const int row = l0 + ty + 16 * i;
            const float v = (acc[i][j] + bv_) * scale;
            if (which == 0) {
                g_qp[row * HH + h] = v;
            } else {
                const int bb_ = row >> 9;         // row / 512
                const int kk_ = row & 511;
                g_cp2T[(bb_ * HH + h) * LK + kk_] = v;
            }
        }
    }
}

// ---------------------------------------------------------------------------
// Kernel B: fused scores(tanh) + softmax + attn@context.
// grid = 128 (32 q-tiles x 4 batches), block = 256 (8 warps).
// MUFU.TANH is the modeled roofline: 134.2M tanh lanes / 16 lanes/cyc/SM.
// ---------------------------------------------------------------------------
__global__ __launch_bounds__(256) void attn_kernel(
    const float* __restrict__ context, const float* __restrict__ Wv,
    float* __restrict__ out)
{
    __shared__ float qp_s[TQ][HH];      // 8KB
    __shared__ float wv_s[HH];
    __shared__ float s_s[TQ][LK];       // 32KB (scores, then exp(p))
    __shared__ float inv_s[TQ];

    const int t    = threadIdx.x;
    const int b    = blockIdx.x & 3;           // batch
    const int q0   = (blockIdx.x >> 2) * TQ;   // q-tile
    const int w    = t >> 5;
    const int lane = t & 31;

    // Stage qp tile + Wv
    for (int u = t; u < TQ * HH; u += 256) {
        const int q = u >> 7, h = u & 127;
        qp_s[q][h] = g_qp[((b * LQ + q0 + q) << 7) + h];
    }
    if (t < HH) wv_s[t] = Wv[t];
    __syncthreads();

    // ---------- Phase 1: scores  (MUFU.TANH-bound) ----------
    // bv is softmax-invariant -> dropped.
    #pragma unroll
    for (int cc = 0; cc < 2; ++cc) {
        const int k = (w + cc * 8) * 32 + lane;                 // 0..511
        const float* __restrict__ cp = g_cp2T + (b << 16) + k;  // + h*512
        float acc[TQ];
        #pragma unroll
        for (int q = 0; q < TQ; ++q) acc[q] = 0.f;

        #pragma unroll 4
        for (int h = 0; h < HH; ++h) {
            const float cv = __ldg(cp + (h << 9));
            const float wv = wv_s[h];
            #pragma unroll
            for (int q = 0; q < TQ; ++q) {
                const float x = cv + qp_s[q][h];
                float tnh;
                asm("tanh.approx.f32 %0, %1;" : "=f"(tnh) : "f"(x));
                acc[q] = fmaf(wv, tnh, acc[q]);
            }
        }
        #pragma unroll
        for (int q = 0; q < TQ; ++q) s_s[q][k] = acc[q];
    }
    __syncthreads();

    // ---------- Phase 2: softmax over k (per row, warp-parallel) ----------
    #pragma unroll
    for (int rr = 0; rr < 2; ++rr) {
        const int row = w + rr * 8;
        float m = -1e30f;
        #pragma unroll
        for (int i = 0; i < 16; ++i) m = fmaxf(m, s_s[row][lane + 32 * i]);
        #pragma unroll
        for (int o = 16; o; o >>= 1) m = fmaxf(m, __shfl_xor_sync(~0u, m, o));
        float sum = 0.f;
        #pragma unroll
        for (int i = 0; i < 16; ++i) {
            const float x = (s_s[row][lane + 32 * i] - m) * 1.4426950408889634f;
            float e;
            asm("ex2.approx.f32 %0, %1;" : "=f"(e) : "f"(x));
            s_s[row][lane + 32 * i] = e;
            sum += e;
        }
        #pragma unroll
        for (int o = 16; o; o >>= 1) sum += __shfl_xor_sync(~0u, sum, o);
        if (lane == 0) inv_s[row] = 1.0f / sum;
    }
    __syncthreads();

    // ---------- Phase 3: out = (p @ context) * inv_sum  (FFMA2) ----------
    // 256 threads = 64 d-groups (4 floats each) x 4 q-groups (4 q each).
    const int dg = t & 63;
    const int qg = t >> 6;
    const int db = dg << 2;
    const float* __restrict__ ctx = context + (b << 17) + db;  // + k*256

    unsigned long long a0[4], a1[4];
    #pragma unroll
    for (int qq = 0; qq < 4; ++qq) { a0[qq] = 0ull; a1[qq] = 0ull; }

    #pragma unroll 4
    for (int k = 0; k < LK; ++k) {
        const float4 c4 = *(const float4*)(ctx + (k << 8));
        unsigned long long cxy, czw;
        asm("mov.b64 %0, {%1, %2};" : "=l"(cxy) : "f"(c4.x), "f"(c4.y));
        asm("mov.b64 %0, {%1, %2};" : "=l"(czw) : "f"(c4.z), "f"(c4.w));
        #pragma unroll
        for (int qq = 0; qq < 4; ++qq) {
            const float p = s_s[qg * 4 + qq][k];   // uniform per warp -> LDS broadcast
            unsigned long long p2;
            asm("mov.b64 %0, {%1, %1};" : "=l"(p2) : "f"(p));
            asm("fma.rn.f32x2 %0, %1, %2, %3;" : "=l"(a0[qq]) : "l"(cxy), "l"(p2), "l"(a0[qq]));
            asm("fma.rn.f32x2 %0, %1, %2, %3;" : "=l"(a1[qq]) : "l"(czw), "l"(p2), "l"(a1[qq]));
        }
    }

    #pragma unroll
    for (int qq = 0; qq < 4; ++qq) {
        const int q = qg * 4 + qq;
        const float inv = inv_s[q];
        float x0, x1, x2, x3;
        asm("mov.b64 {%0, %1}, %2;" : "=f"(x0), "=f"(x1) : "l"(a0[qq]));
        asm("mov.b64 {%0, %1}, %2;" : "=f"(x2), "=f"(x3) : "l"(a1[qq]));
        float4 o4 = make_float4(x0 * inv, x1 * inv, x2 * inv, x3 * inv);
        *(float4*)&out[((b * LQ + q0 + q) << 8) + db] = o4;
    }
}

// ---------------------------------------------------------------------------
extern "C" void kernel_launch(void* const* d_in, const int* in_sizes, int n_in,
                              void* d_out, int out_size)
{
    const float* query   = (const float*)d_in[0];
    const float* context = (const float*)d_in[1];
    const float* Wq      = (const float*)d_in[2];
    const float* bq      = (const float*)d_in[3];
    const float* Wc      = (const float*)d_in[4];
    const float* bc      = (const float*)d_in[5];
    const float* Wv      = (const float*)d_in[6];
    // d_in[7] = bv : softmax-invariant, unused.
    float* out = (float*)d_out;

    dim3 gA(2048 / 64, 2);
    proj_kernel<<<gA, 256>>>(query, context, Wq, bq, Wc, bc);

    attn_kernel<<<128, 256>>>(context, Wv, out);
}

// round 6
// speedup vs baseline: 1.1767x; 1.1767x over previous
#include <cuda_runtime.h>
#include <cuda_bf16.h>

// Problem constants
#define BB   4
#define LQ   512
#define LK   512
#define DD   256
#define HH   128
#define TQ   16          // q-rows per CTA in attention kernel

// Scratch (static device memory — allocation-free rule)
__device__ float g_qp[BB * LQ * HH];          // [b*512+q][h]   row-major, 1MB
__device__ float g_cp2T[BB * HH * LK];        // [b][h][k]      transposed, 1MB

// ---------------------------------------------------------------------------
// Kernel A: projections (~8-10us, not the bottleneck).
// ---------------------------------------------------------------------------
__global__ __launch_bounds__(256) void proj_kernel(
    const float* __restrict__ query, const float* __restrict__ context,
    const float* __restrict__ Wq, const float* __restrict__ bq,
    const float* __restrict__ Wc, const float* __restrict__ bc)
{
    const int which = blockIdx.y;
    const float* __restrict__ src  = which ? context : query;
    const float* __restrict__ W    = which ? Wc : Wq;
    const float* __restrict__ bias = which ? bc : bq;
    const float scale = which ? 2.0f : 1.0f;

    __shared__ float As[32][65];
    __shared__ float Bs[32][129];

    const int t  = threadIdx.x;
    const int tx = t & 15;
    const int ty = t >> 4;
    const int l0 = blockIdx.x * 64;

    float acc[4][8];
    #pragma unroll
    for (int i = 0; i < 4; ++i)
        #pragma unroll
        for (int j = 0; j < 8; ++j) acc[i][j] = 0.f;

    for (int it = 0; it < 8; ++it) {
        const int k0 = it * 32;
        {
            const int r  = t >> 3;
            const int c4 = (t & 7) * 4;
            #pragma unroll
            for (int p = 0; p < 2; ++p) {
                const int row = r + p * 32;
                float4 v = *(const float4*)&src[(l0 + row) * DD + k0 + c4];
                As[c4 + 0][row] = v.x; As[c4 + 1][row] = v.y;
                As[c4 + 2][row] = v.z; As[c4 + 3][row] = v.w;
            }
        }
        {
            const int h = t >> 1;
            #pragma unroll
            for (int j = 0; j < 4; ++j) {
                const int f = (t & 1) * 4 + j;
                float4 v = __ldg((const float4*)&W[h * DD + k0 + f * 4]);
                Bs[f * 4 + 0][h] = v.x; Bs[f * 4 + 1][h] = v.y;
                Bs[f * 4 + 2][h] = v.z; Bs[f * 4 + 3][h] = v.w;
            }
        }
        __syncthreads();
        #pragma unroll
        for (int kk = 0; kk < 32; ++kk) {
            float a[4], bb[8];
            #pragma unroll
            for (int i = 0; i < 4; ++i) a[i] = As[kk][ty + 16 * i];
            #pragma unroll
            for (int j = 0; j < 8; ++j) bb[j] = Bs[kk][tx + 16 * j];
            #pragma unroll
            for (int i = 0; i < 4; ++i)
                #pragma unroll
                for (int j = 0; j < 8; ++j) acc[i][j] = fmaf(a[i], bb[j], acc[i][j]);
        }
        __syncthreads();
    }

    #pragma unroll
    for (int j = 0; j < 8; ++j) {
        const int h = tx + 16 * j;
        const float bv_ = bias[h];
        #pragma unroll
        for (int i = 0; i < 4; ++i) {
            const int row = l0 + ty + 16 * i;
            const float v = (acc[i][j] + bv_) * scale;
            if (which == 0) {
                g_qp[row * HH + h] = v;
            } else {
                const int bb_ = row >> 9;
                const int kk_ = row & 511;
                g_cp2T[(bb_ * HH + h) * LK + kk_] = v;
            }
        }
    }
}

// ---------------------------------------------------------------------------
// Kernel B: fused scores(tanh) + softmax + attn@context.
// grid = 128, block = 512 (16 warps -> 4 warps/SMSP for latency hiding).
// MUFU floor per SM: 64 MUFU/SMSP/h-iter x rt8 = 512cyc; other issue ~300cyc.
// ---------------------------------------------------------------------------
__global__ __launch_bounds__(512) void attn_kernel(
    const float* __restrict__ context, const float* __restrict__ Wv,
    float* __restrict__ out)
{
    __shared__ float qpT_s[HH][TQ];     // TRANSPOSED: [h][q], 8KB -> LDS.128 over q
    __shared__ float wv_s[HH];
    __shared__ float s_s[TQ][LK];       // 32KB (scores, then exp(p))
    __shared__ float inv_s[TQ];

    const int t    = threadIdx.x;
    const int b    = blockIdx.x & 3;           // batch
    const int q0   = (blockIdx.x >> 2) * TQ;   // q-tile
    const int w    = t >> 5;
    const int lane = t & 31;

    // Stage qp tile (transposed) + Wv
    for (int u = t; u < TQ * HH; u += 512) {
        const int q = u >> 7, h = u & 127;
        qpT_s[h][q] = g_qp[((b * LQ + q0 + q) << 7) + h];
    }
    if (t < HH) wv_s[t] = Wv[t];
    __syncthreads();

    // ---------- Phase 1: scores. k == t (16 warps x 32 lanes = 512 k). ----------
    {
        const float* __restrict__ cp = g_cp2T + (b << 16) + t;  // + h*512
        float acc[TQ];
        #pragma unroll
        for (int q = 0; q < TQ; ++q) acc[q] = 0.f;

        #pragma unroll 4
        for (int h = 0; h < HH; ++h) {
            const float cv = __ldg(cp + (h << 9));
            const float wv = wv_s[h];
            float4 qv[4];
            #pragma unroll
            for (int g = 0; g < 4; ++g)
                qv[g] = *(const float4*)&qpT_s[h][g * 4];   // broadcast LDS.128
            const float* qf = (const float*)qv;
            #pragma unroll
            for (int q = 0; q < TQ; ++q) {
                const float x = cv + qf[q];
                float tnh;
                asm("tanh.approx.f32 %0, %1;" : "=f"(tnh) : "f"(x));
                acc[q] = fmaf(wv, tnh, acc[q]);
            }
        }
        #pragma unroll
        for (int q = 0; q < TQ; ++q) s_s[q][t] = acc[q];
    }
    __syncthreads();

    // ---------- Phase 2: softmax over k (one warp per row) ----------
    {
        const int row = w;   // 16 warps, 16 rows
        float m = -1e30f;
        #pragma unroll
        for (int i = 0; i < 16; ++i) m = fmaxf(m, s_s[row][lane + 32 * i]);
        #pragma unroll
        for (int o = 16; o; o >>= 1) m = fmaxf(m, __shfl_xor_sync(~0u, m, o));
        float sum = 0.f;
        #pragma unroll
        for (int i = 0; i < 16; ++i) {
            const float x = (s_s[row][lane + 32 * i] - m) * 1.4426950408889634f;
            float e;
            asm("ex2.approx.f32 %0, %1;" : "=f"(e) : "f"(x));
            s_s[row][lane + 32 * i] = e;
            sum += e;
        }
        #pragma unroll
        for (int o = 16; o; o >>= 1) sum += __shfl_xor_sync(~0u, sum, o);
        if (lane == 0) inv_s[row] = 1.0f / sum;
    }
    __syncthreads();

    // ---------- Phase 3: out = (p @ context) * inv_sum  (FFMA2) ----------
    // 512 threads = 64 d-groups (4 floats) x 8 q-groups (2 q each).
    const int dg = t & 63;
    const int qg = t >> 6;          // 0..7, constant within a warp
    const int db = dg << 2;
    const float* __restrict__ ctx = context + (b << 17) + db;  // + k*256

    unsigned long long a0[2], a1[2];
    #pragma unroll
    for (int qq = 0; qq < 2; ++qq) { a0[qq] = 0ull; a1[qq] = 0ull; }

    #pragma unroll 4
    for (int k = 0; k < LK; ++k) {
        const float4 c4 = *(const float4*)(ctx + (k << 8));
        unsigned long long cxy, czw;
        asm("mov.b64 %0, {%1, %2};" : "=l"(cxy) : "f"(c4.x), "f"(c4.y));
        asm("mov.b64 %0, {%1, %2};" : "=l"(czw) : "f"(c4.z), "f"(c4.w));
        #pragma unroll
        for (int qq = 0; qq < 2; ++qq) {
            const float p = s_s[qg * 2 + qq][k];   // warp-uniform -> LDS broadcast
            unsigned long long p2;
            asm("mov.b64 %0, {%1, %1};" : "=l"(p2) : "f"(p));
            asm("fma.rn.f32x2 %0, %1, %2, %3;" : "=l"(a0[qq]) : "l"(cxy), "l"(p2), "l"(a0[qq]));
            asm("fma.rn.f32x2 %0, %1, %2, %3;" : "=l"(a1[qq]) : "l"(czw), "l"(p2), "l"(a1[qq]));
        }
    }

    #pragma unroll
    for (int qq = 0; qq < 2; ++qq) {
        const int q = qg * 2 + qq;
        const float inv = inv_s[q];
        float x0, x1, x2, x3;
        asm("mov.b64 {%0, %1}, %2;" : "=f"(x0), "=f"(x1) : "l"(a0[qq]));
        asm("mov.b64 {%0, %1}, %2;" : "=f"(x2), "=f"(x3) : "l"(a1[qq]));
        float4 o4 = make_float4(x0 * inv, x1 * inv, x2 * inv, x3 * inv);
        *(float4*)&out[((b * LQ + q0 + q) << 8) + db] = o4;
    }
}

// ---------------------------------------------------------------------------
extern "C" void kernel_launch(void* const* d_in, const int* in_sizes, int n_in,
                              void* d_out, int out_size)
{
    const float* query   = (const float*)d_in[0];
    const float* context = (const float*)d_in[1];
    const float* Wq      = (const float*)d_in[2];
    const float* bq      = (const float*)d_in[3];
    const float* Wc      = (const float*)d_in[4];
    const float* bc      = (const float*)d_in[5];
    const float* Wv      = (const float*)d_in[6];
    // d_in[7] = bv : softmax-invariant, unused.
    float* out = (float*)d_out;

    dim3 gA(2048 / 64, 2);
    proj_kernel<<<gA, 256>>>(query, context, Wq, bq, Wc, bc);

    attn_kernel<<<128, 512>>>(context, Wv, out);
}